// round 13
// baseline (speedup 1.0000x reference)
#include <cuda_runtime.h>
#include <cuda_fp16.h>
#include <stdint.h>

#define BATCH 4
#define SEQ   2048
#define DIM   768
#define MROWS 8192            // B*S
#define NQKV  2304            // 3*DIM

// ---------------- device scratch: single fp16 planes --------------------------
__device__ __align__(128) __half g_x16[(long)MROWS * DIM];
__device__ __align__(128) __half g_w16[(long)NQKV * DIM];
__device__ __align__(128) __half g_q16[(long)MROWS * DIM];
__device__ __align__(128) __half g_k16[(long)MROWS * DIM];
__device__ __align__(128) __half g_v16[(long)MROWS * DIM];          // [b*S+s][d]
__device__ __align__(128) __half g_p16[(size_t)BATCH * SEQ * SEQ];
__device__ float g_S[(size_t)BATCH * SEQ * SEQ];

// ---------------- PTX helpers (portable, no arch-'a' features) --------------
__device__ __forceinline__ uint32_t smem_u32(const void* p) {
    uint32_t a;
    asm("{ .reg .u64 t; cvta.to.shared.u64 t, %1; cvt.u32.u64 %0, t; }"
        : "=r"(a) : "l"(p));
    return a;
}
__device__ __forceinline__ void ldsm4(uint32_t r[4], uint32_t addr) {
    asm volatile("ldmatrix.sync.aligned.m8n8.x4.shared.b16 {%0,%1,%2,%3}, [%4];"
                 : "=r"(r[0]), "=r"(r[1]), "=r"(r[2]), "=r"(r[3]) : "r"(addr));
}
__device__ __forceinline__ void ldsm4t(uint32_t r[4], uint32_t addr) {
    asm volatile("ldmatrix.sync.aligned.m8n8.x4.trans.shared.b16 {%0,%1,%2,%3}, [%4];"
                 : "=r"(r[0]), "=r"(r[1]), "=r"(r[2]), "=r"(r[3]) : "r"(addr));
}
__device__ __forceinline__ void mma16816(float d[4], const uint32_t a[4],
                                         const uint32_t b[2]) {
    asm volatile(
        "mma.sync.aligned.m16n8k16.row.col.f32.f16.f16.f32 "
        "{%0,%1,%2,%3}, {%4,%5,%6,%7}, {%8,%9}, {%0,%1,%2,%3};"
        : "+f"(d[0]), "+f"(d[1]), "+f"(d[2]), "+f"(d[3])
        : "r"(a[0]), "r"(a[1]), "r"(a[2]), "r"(a[3]), "r"(b[0]), "r"(b[1]));
}
__device__ __forceinline__ void cpa16(uint32_t dst, const void* src) {
    asm volatile("cp.async.cg.shared.global [%0], [%1], 16;" :: "r"(dst), "l"(src));
}
__device__ __forceinline__ void cp_commit() {
    asm volatile("cp.async.commit_group;" ::: "memory");
}
template <int N> __device__ __forceinline__ void cp_wait() {
    asm volatile("cp.async.wait_group %0;" :: "n"(N) : "memory");
}

// ---------------- smem geometry: k32 stages, 3-stage cp.async ring ------------
#define ROW2B   80
#define PLANE2  10240                      // 128*80
#define NT_STG  (2 * PLANE2)               // A + B = 20480
#define NT_SMEM (3 * NT_STG)               // 61440

#define VROWB   272
#define VPLANE2 (32 * VROWB)               // 8704 (V plane, 32 rows x 128 cols)
#define PV_STG  (PLANE2 + VPLANE2)         // 18944
#define PV_SMEM (3 * PV_STG)               // 56832

// ---------------- stage compute: warp tile 64x64, one k16 sub-block ----------
__device__ __forceinline__ void stage_nt(uint32_t sa, uint32_t sb, int sub, int lane,
                                         int wm, int wn, float acc[4][8][4]) {
    const int lr = lane & 15;
    const uint32_t lc16 = ((lane >> 4) << 4) + (uint32_t)sub * 32;
    uint32_t bh[8][2];
#pragma unroll
    for (int j = 0; j < 4; ++j) {
        uint32_t t4[4];
        const uint32_t roff = (uint32_t)(wn * 64 + j * 16 + lr) * ROW2B + lc16;
        ldsm4(t4, sb + roff);
        bh[j*2][0] = t4[0]; bh[j*2+1][0] = t4[1];
        bh[j*2][1] = t4[2]; bh[j*2+1][1] = t4[3];
    }
#pragma unroll
    for (int mi = 0; mi < 4; ++mi) {
        uint32_t ah[4];
        const uint32_t roff = (uint32_t)(wm * 64 + mi * 16 + lr) * ROW2B + lc16;
        ldsm4(ah, sa + roff);
#pragma unroll
        for (int nj = 0; nj < 8; ++nj)
            mma16816(acc[mi][nj], ah, bh[nj]);
    }
}

__device__ __forceinline__ void stage_pv(uint32_t sa, uint32_t sv, int sub, int lane,
                                         int wm, int wn, float acc[4][8][4]) {
    const int lr = lane & 15;
    const uint32_t lc16 = (lane >> 4) << 4;
    const uint32_t pc16 = lc16 + (uint32_t)sub * 32;
    uint32_t bh[8][2];
#pragma unroll
    for (int j = 0; j < 4; ++j) {
        uint32_t t4[4];
        const uint32_t off = (uint32_t)(sub * 16 + lr) * VROWB +
                             (uint32_t)(wn * 64 + j * 16) * 2 + lc16;
        ldsm4t(t4, sv + off);
        bh[j*2][0] = t4[0]; bh[j*2][1] = t4[1];
        bh[j*2+1][0] = t4[2]; bh[j*2+1][1] = t4[3];
    }
#pragma unroll
    for (int mi = 0; mi < 4; ++mi) {
        uint32_t ah[4];
        const uint32_t roff = (uint32_t)(wm * 64 + mi * 16 + lr) * ROW2B + pc16;
        ldsm4(ah, sa + roff);
#pragma unroll
        for (int nj = 0; nj < 8; ++nj)
            mma16816(acc[mi][nj], ah, bh[nj]);
    }
}

#define ACC_INIT float acc[4][8][4];                                    \
    _Pragma("unroll") for (int _i = 0; _i < 4; ++_i)                    \
    _Pragma("unroll") for (int _j = 0; _j < 8; ++_j)                    \
    _Pragma("unroll") for (int _k = 0; _k < 4; ++_k) acc[_i][_j][_k] = 0.f;

// ---------------- cp.async k32 stage issue (128 threads, reg-free staging) ---
__device__ __forceinline__ void issue_nt(uint32_t sbase, int tid,
                                         const __half* A, const __half* B,
                                         long lda, long ldb, int k0) {
    const uint32_t so = sbase + (uint32_t)tid * ROW2B;
    const long ga = (long)tid * lda + k0;
    const long gb = (long)tid * ldb + k0;
#pragma unroll
    for (int i = 0; i < 4; ++i) {
        cpa16(so + i * 16,          A + ga + i * 8);
        cpa16(so + PLANE2 + i * 16, B + gb + i * 8);
    }
}
__device__ __forceinline__ void issue_pv(uint32_t sbase, int tid,
                                         const __half* P, const __half* V,
                                         int n0, int k0) {
    const uint32_t so = sbase + (uint32_t)tid * ROW2B;
    const long gp = (long)tid * SEQ + k0;
#pragma unroll
    for (int i = 0; i < 4; ++i)
        cpa16(so + i * 16, P + gp + i * 8);
    const int vr = tid >> 2;                 // 32 rows, 4 threads/row
    const int vc = (tid & 3) * 32;           // halves (64B per thread)
    const uint32_t vo = sbase + PLANE2 + (uint32_t)vr * VROWB + (uint32_t)vc * 2;
    const long gv = (long)(k0 + vr) * DIM + n0 + vc;
#pragma unroll
    for (int i = 0; i < 4; ++i)
        cpa16(vo + i * 16, V + gv + i * 8);
}

// ---------------- kernel 0a: x -> fp16 plane ----------------------------------
__global__ __launch_bounds__(256) void cvt_x(const float* __restrict__ src) {
    const long i = ((long)blockIdx.x * 256 + threadIdx.x) * 4;
    const float4 v = *(const float4*)(src + i);
    __half h[4] = { __float2half_rn(v.x), __float2half_rn(v.y),
                    __float2half_rn(v.z), __float2half_rn(v.w) };
    *(uint2*)(g_x16 + i) = *(uint2*)h;
}

// ---------------- kernel 0b: Wq|Wk|Wv -> fp16 plane (one launch) ---------------
__global__ __launch_bounds__(256) void cvt_w(const float* __restrict__ wq,
                                             const float* __restrict__ wk,
                                             const float* __restrict__ wv) {
    const int mat = blockIdx.y;
    const float* src = (mat == 0) ? wq : ((mat == 1) ? wk : wv);
    const long i = ((long)blockIdx.x * 256 + threadIdx.x) * 4;
    const long o = (long)mat * DIM * DIM + i;
    const float4 v = *(const float4*)(src + i);
    __half h[4] = { __float2half_rn(v.x), __float2half_rn(v.y),
                    __float2half_rn(v.z), __float2half_rn(v.w) };
    *(uint2*)(g_w16 + o) = *(uint2*)h;
}

// ---------------- NT mainloop: 3-stage cp.async ring, ONE sync per k32 --------
// Order inside the loop is hazard-safe: wait(stage c ready) -> barrier (all
// warps done with stage c-1) -> refill stage c+2 (== slot c-1) -> compute c.
#define NT_BODY(A, B, lda, ldb, NC2)                                           \
    extern __shared__ __align__(128) char dsm[];                               \
    const int tid = threadIdx.x;                                               \
    const int lane = tid & 31, wid = tid >> 5;                                 \
    const int wm = wid >> 1, wn = wid & 1;                                     \
    const uint32_t su = smem_u32(dsm);                                         \
    ACC_INIT;                                                                  \
    issue_nt(su,              tid, A, B, lda, ldb, 0);  cp_commit();           \
    issue_nt(su + NT_STG,     tid, A, B, lda, ldb, 32); cp_commit();           \
    for (int c = 0; c < (NC2); ++c) {                                          \
        cp_wait<1>();                                                          \
        __syncthreads();                                                       \
        if (c + 2 < (NC2))                                                     \
            issue_nt(su + ((c + 2) % 3) * NT_STG, tid, A, B, lda, ldb,         \
                     (c + 2) * 32);                                            \
        cp_commit();                                                           \
        const uint32_t sb0 = su + (c % 3) * NT_STG;                            \
        stage_nt(sb0, sb0 + PLANE2, 0, lane, wm, wn, acc);                     \
        stage_nt(sb0, sb0 + PLANE2, 1, lane, wm, wn, acc);                     \
    }

// ---------------- kernel 1: QKV projection (NT) -------------------------------
__global__ __launch_bounds__(128, 3) void gemm_qkv() {
    const int m0 = blockIdx.x * 128;
    const int n0 = blockIdx.y * 128;
    NT_BODY(g_x16 + (long)m0 * DIM, g_w16 + (long)n0 * DIM, DIM, DIM, DIM / 32);

    const int mat = n0 / DIM;
    const int nl0 = n0 % DIM;
    __half* dst = (mat == 0) ? g_q16 : ((mat == 1) ? g_k16 : g_v16);
    const int r = lane >> 2, cc = (lane & 3) * 2;
#pragma unroll
    for (int mi = 0; mi < 4; ++mi)
#pragma unroll
        for (int nj = 0; nj < 8; ++nj)
#pragma unroll
            for (int h2 = 0; h2 < 2; ++h2) {
                const int m = m0 + wm * 64 + mi * 16 + r + h2 * 8;
                const int n = nl0 + wn * 64 + nj * 8 + cc;
                *(__half2*)(dst + (long)m * DIM + n) =
                    __halves2half2(__float2half_rn(acc[mi][nj][h2 * 2 + 0]),
                                   __float2half_rn(acc[mi][nj][h2 * 2 + 1]));
            }
}

// ---------------- kernel 2: causal scores (NT) --------------------------------
__global__ __launch_bounds__(128, 3) void gemm_scores() {
    const int mi_t = gridDim.x - 1 - blockIdx.x;    // longest first
    if ((int)blockIdx.y > mi_t) return;             // fully above diagonal
    const int m0 = mi_t * 128, n0 = blockIdx.y * 128, b = blockIdx.z;
    NT_BODY(g_q16 + ((long)b * SEQ + m0) * DIM,
            g_k16 + ((long)b * SEQ + n0) * DIM, DIM, DIM, DIM / 32);

    const float scale = 0.036084391824351615f;      // 1/sqrt(768)
    float* Sg = g_S + (size_t)b * SEQ * SEQ;
    const int r = lane >> 2, cc = (lane & 3) * 2;
#pragma unroll
    for (int mi = 0; mi < 4; ++mi)
#pragma unroll
        for (int nj = 0; nj < 8; ++nj)
#pragma unroll
            for (int h2 = 0; h2 < 2; ++h2) {
                const int m = m0 + wm * 64 + mi * 16 + r + h2 * 8;
                const int n = n0 + wn * 64 + nj * 8 + cc;
                float2 v = make_float2(acc[mi][nj][h2 * 2 + 0] * scale,
                                       acc[mi][nj][h2 * 2 + 1] * scale);
                *(float2*)(Sg + (size_t)m * SEQ + n) = v;
            }
}

// ---------------- kernel 3: softmax + fp16 P -----------------------------------
__global__ __launch_bounds__(256) void softmax_kernel() {
    const int rid = blockIdx.x;
    const int q = rid & (SEQ - 1);
    float* __restrict__ row = g_S + (size_t)rid * SEQ;
    __half* __restrict__ ph = g_p16 + (size_t)rid * SEQ;
    const int L = q + 1;
    const int tid = threadIdx.x;
    __shared__ float red[256];

    float m = -1e30f;
    for (int k = tid; k < L; k += 256) m = fmaxf(m, row[k]);
    red[tid] = m;
    __syncthreads();
#pragma unroll
    for (int s = 128; s > 0; s >>= 1) {
        if (tid < s) red[tid] = fmaxf(red[tid], red[tid + s]);
        __syncthreads();
    }
    m = red[0];
    __syncthreads();

    float ssum = 0.f;
    for (int k = tid; k < L; k += 256) {
        float e = __expf(row[k] - m);
        row[k] = e;
        ssum += e;
    }
    red[tid] = ssum;
    __syncthreads();
#pragma unroll
    for (int s = 128; s > 0; s >>= 1) {
        if (tid < s) red[tid] += red[tid + s];
        __syncthreads();
    }
    const float inv = 1.0f / red[0];

    for (int k = tid; k < L; k += 256)
        ph[k] = __float2half_rn(row[k] * inv);
    const int kend = (q & ~127) + 128;
    const __half z = __float2half_rn(0.f);
    for (int k = L + tid; k < kend; k += 256) ph[k] = z;
}

// ---------------- kernel 4: O = P V --------------------------------------------
__global__ __launch_bounds__(128, 3) void gemm_pv(float* __restrict__ out) {
    const int mi_t = gridDim.x - 1 - blockIdx.x;    // longest K first
    const int m0 = mi_t * 128, n0 = blockIdx.y * 128, b = blockIdx.z;
    const __half* P = g_p16 + ((size_t)b * SEQ + m0) * SEQ;
    const __half* V = g_v16 + (long)b * SEQ * DIM;

    extern __shared__ __align__(128) char dsm[];
    const int tid = threadIdx.x;
    const int lane = tid & 31, wid = tid >> 5;
    const int wm = wid >> 1, wn = wid & 1;
    const uint32_t su = smem_u32(dsm);
    ACC_INIT;
    const int NC2 = (m0 + 128) / 32;                // >= 4 always

    issue_pv(su,          tid, P, V, n0, 0);  cp_commit();
    issue_pv(su + PV_STG, tid, P, V, n0, 32); cp_commit();
    for (int c = 0; c < NC2; ++c) {
        cp_wait<1>();
        __syncthreads();
        if (c + 2 < NC2)
            issue_pv(su + ((c + 2) % 3) * PV_STG, tid, P, V, n0, (c + 2) * 32);
        cp_commit();
        const uint32_t sb0 = su + (c % 3) * PV_STG;
        stage_pv(sb0, sb0 + PLANE2, 0, lane, wm, wn, acc);
        stage_pv(sb0, sb0 + PLANE2, 1, lane, wm, wn, acc);
    }

    float* Og = out + (long)b * SEQ * DIM;
    const int r = lane >> 2, cc = (lane & 3) * 2;
#pragma unroll
    for (int mi = 0; mi < 4; ++mi)
#pragma unroll
        for (int nj = 0; nj < 8; ++nj)
#pragma unroll
            for (int h2 = 0; h2 < 2; ++h2) {
                const int m = m0 + wm * 64 + mi * 16 + r + h2 * 8;
                const int n = n0 + wn * 64 + nj * 8 + cc;
                float2 v = make_float2(acc[mi][nj][h2 * 2 + 0],
                                       acc[mi][nj][h2 * 2 + 1]);
                *(float2*)(Og + (long)m * DIM + n) = v;
            }
}

// ---------------- launch ---------------------------------------------------------
extern "C" void kernel_launch(void* const* d_in, const int* in_sizes, int n_in,
                              void* d_out, int out_size) {
    const float* x  = (const float*)d_in[0];
    const float* Wq = (const float*)d_in[1];
    const float* Wk = (const float*)d_in[2];
    const float* Wv = (const float*)d_in[3];
    float* out = (float*)d_out;

    cudaFuncSetAttribute(gemm_qkv,    cudaFuncAttributeMaxDynamicSharedMemorySize, NT_SMEM);
    cudaFuncSetAttribute(gemm_scores, cudaFuncAttributeMaxDynamicSharedMemorySize, NT_SMEM);
    cudaFuncSetAttribute(gemm_pv,     cudaFuncAttributeMaxDynamicSharedMemorySize, PV_SMEM);

    cvt_x<<<(long)MROWS * DIM / 4 / 256, 256>>>(x);
    cvt_w<<<dim3(DIM * DIM / 4 / 256, 3), 256>>>(Wq, Wk, Wv);

    gemm_qkv<<<dim3(MROWS / 128, NQKV / 128), 128, NT_SMEM>>>();
    gemm_scores<<<dim3(SEQ / 128, SEQ / 128, BATCH), 128, NT_SMEM>>>();
    softmax_kernel<<<BATCH * SEQ, 256>>>();
    gemm_pv<<<dim3(SEQ / 128, DIM / 128, BATCH), 128, PV_SMEM>>>(out);
}

// round 15
// speedup vs baseline: 1.1594x; 1.1594x over previous
#include <cuda_runtime.h>
#include <cuda_fp16.h>
#include <stdint.h>

#define BATCH 4
#define SEQ   2048
#define DIM   768
#define MROWS 8192            // B*S
#define NQKV  2304            // 3*DIM

// ---------------- device scratch: single fp16 planes --------------------------
__device__ __align__(128) __half g_x16[(long)MROWS * DIM];
__device__ __align__(128) __half g_w16[(long)NQKV * DIM];
__device__ __align__(128) __half g_q16[(long)MROWS * DIM];
__device__ __align__(128) __half g_k16[(long)MROWS * DIM];
__device__ __align__(128) __half g_v16[(long)MROWS * DIM];          // [b*S+s][d]
__device__ __align__(128) __half g_p16[(size_t)BATCH * SEQ * SEQ];
__device__ float g_S[(size_t)BATCH * SEQ * SEQ];

// ---------------- PTX helpers (portable, no arch-'a' features) --------------
__device__ __forceinline__ uint32_t smem_u32(const void* p) {
    uint32_t a;
    asm("{ .reg .u64 t; cvta.to.shared.u64 t, %1; cvt.u32.u64 %0, t; }"
        : "=r"(a) : "l"(p));
    return a;
}
__device__ __forceinline__ void ldsm4(uint32_t r[4], uint32_t addr) {
    asm volatile("ldmatrix.sync.aligned.m8n8.x4.shared.b16 {%0,%1,%2,%3}, [%4];"
                 : "=r"(r[0]), "=r"(r[1]), "=r"(r[2]), "=r"(r[3]) : "r"(addr));
}
__device__ __forceinline__ void ldsm4t(uint32_t r[4], uint32_t addr) {
    asm volatile("ldmatrix.sync.aligned.m8n8.x4.trans.shared.b16 {%0,%1,%2,%3}, [%4];"
                 : "=r"(r[0]), "=r"(r[1]), "=r"(r[2]), "=r"(r[3]) : "r"(addr));
}
__device__ __forceinline__ void mma16816(float d[4], const uint32_t a[4],
                                         const uint32_t b[2]) {
    asm volatile(
        "mma.sync.aligned.m16n8k16.row.col.f32.f16.f16.f32 "
        "{%0,%1,%2,%3}, {%4,%5,%6,%7}, {%8,%9}, {%0,%1,%2,%3};"
        : "+f"(d[0]), "+f"(d[1]), "+f"(d[2]), "+f"(d[3])
        : "r"(a[0]), "r"(a[1]), "r"(a[2]), "r"(a[3]), "r"(b[0]), "r"(b[1]));
}

// ---------------- smem geometry: k64 stages, double buffered ------------------
// tiles: 128 rows x 64 k fp16, pitch 72 halves = 144 B.
// 144 is 16B-aligned; 144 mod 128 = 16 -> within an 8-row ldmatrix group the
// row bases hit offsets 0,16,...,112 mod 128: each 16B bank segment once ->
// conflict-free, and every uint4/ldmatrix address stays 16B-aligned.
#define ROW4B   144
#define PLANE4  18432                      // 128*144
#define NT_STG  (2 * PLANE4)               // A + B = 36864
#define NT_SMEM (2 * NT_STG)               // 73728

#define VROWB   272
#define VPLANE4 (64 * VROWB)               // 17408 (V plane, 64 rows x 128 cols)
#define PV_STG  (PLANE4 + VPLANE4)         // 35840
#define PV_SMEM (2 * PV_STG)               // 71680

// ---------------- stage compute: warp tile 64x64, one k16 sub (0..3) ----------
__device__ __forceinline__ void stage_nt(uint32_t sa, uint32_t sb, int sub, int lane,
                                         int wm, int wn, float acc[4][8][4]) {
    const int lr = lane & 15;
    const uint32_t lc16 = ((lane >> 4) << 4) + (uint32_t)sub * 32;
    uint32_t bh[8][2];
#pragma unroll
    for (int j = 0; j < 4; ++j) {
        uint32_t t4[4];
        const uint32_t roff = (uint32_t)(wn * 64 + j * 16 + lr) * ROW4B + lc16;
        ldsm4(t4, sb + roff);
        bh[j*2][0] = t4[0]; bh[j*2+1][0] = t4[1];
        bh[j*2][1] = t4[2]; bh[j*2+1][1] = t4[3];
    }
#pragma unroll
    for (int mi = 0; mi < 4; ++mi) {
        uint32_t ah[4];
        const uint32_t roff = (uint32_t)(wm * 64 + mi * 16 + lr) * ROW4B + lc16;
        ldsm4(ah, sa + roff);
#pragma unroll
        for (int nj = 0; nj < 8; ++nj)
            mma16816(acc[mi][nj], ah, bh[nj]);
    }
}

__device__ __forceinline__ void stage_pv(uint32_t sa, uint32_t sv, int sub, int lane,
                                         int wm, int wn, float acc[4][8][4]) {
    const int lr = lane & 15;
    const uint32_t lc16 = (lane >> 4) << 4;
    const uint32_t pc16 = lc16 + (uint32_t)sub * 32;
    uint32_t bh[8][2];
#pragma unroll
    for (int j = 0; j < 4; ++j) {
        uint32_t t4[4];
        const uint32_t off = (uint32_t)(sub * 16 + lr) * VROWB +
                             (uint32_t)(wn * 64 + j * 16) * 2 + lc16;
        ldsm4t(t4, sv + off);
        bh[j*2][0] = t4[0]; bh[j*2][1] = t4[1];
        bh[j*2+1][0] = t4[2]; bh[j*2+1][1] = t4[3];
    }
#pragma unroll
    for (int mi = 0; mi < 4; ++mi) {
        uint32_t ah[4];
        const uint32_t roff = (uint32_t)(wm * 64 + mi * 16 + lr) * ROW4B + pc16;
        ldsm4(ah, sa + roff);
#pragma unroll
        for (int nj = 0; nj < 8; ++nj)
            mma16816(acc[mi][nj], ah, bh[nj]);
    }
}

#define ACC_INIT float acc[4][8][4];                                    \
    _Pragma("unroll") for (int _i = 0; _i < 4; ++_i)                    \
    _Pragma("unroll") for (int _j = 0; _j < 8; ++_j)                    \
    _Pragma("unroll") for (int _k = 0; _k < 4; ++_k) acc[_i][_j][_k] = 0.f;

// ---------------- k16 sub-fill loaders (128 threads, 16-reg rolling prefetch) -
struct Frag4 { uint4 v[4]; };

__device__ __forceinline__ Frag4 ld16_nt(const __half* A, const __half* B,
                                         long lda, long ldb, int k0, int tid) {
    const long ga = (long)tid * lda + k0;
    const long gb = (long)tid * ldb + k0;
    Frag4 f;
    f.v[0] = *(const uint4*)(A + ga);
    f.v[1] = *(const uint4*)(A + ga + 8);
    f.v[2] = *(const uint4*)(B + gb);
    f.v[3] = *(const uint4*)(B + gb + 8);
    return f;
}
__device__ __forceinline__ void st16_nt(char* dsm, int stg, int sub, Frag4 f, int tid) {
    char* base = dsm + stg * NT_STG;
    const uint32_t so = (uint32_t)tid * ROW4B + (uint32_t)sub * 32;
    *(uint4*)(base + so)               = f.v[0];
    *(uint4*)(base + so + 16)          = f.v[1];
    *(uint4*)(base + PLANE4 + so)      = f.v[2];
    *(uint4*)(base + PLANE4 + so + 16) = f.v[3];
}

__device__ __forceinline__ Frag4 ld16_pv(const __half* P, const __half* V,
                                         int n0, int k0, int tid) {
    const long gp = (long)tid * SEQ + k0;
    const int vr = tid >> 3, vc = (tid & 7) * 16;
    const long gv = (long)(k0 + vr) * DIM + n0 + vc;
    Frag4 f;
    f.v[0] = *(const uint4*)(P + gp);
    f.v[1] = *(const uint4*)(P + gp + 8);
    f.v[2] = *(const uint4*)(V + gv);
    f.v[3] = *(const uint4*)(V + gv + 8);
    return f;
}
__device__ __forceinline__ void st16_pv(char* dsm, int stg, int sub, Frag4 f, int tid) {
    char* base = dsm + stg * PV_STG;
    const uint32_t so = (uint32_t)tid * ROW4B + (uint32_t)sub * 32;
    *(uint4*)(base + so)      = f.v[0];
    *(uint4*)(base + so + 16) = f.v[1];
    const int vr = tid >> 3, vc = (tid & 7) * 16;
    const uint32_t vo = (uint32_t)(sub * 16 + vr) * VROWB + (uint32_t)vc * 2;
    *(uint4*)(base + PLANE4 + vo)      = f.v[2];
    *(uint4*)(base + PLANE4 + vo + 16) = f.v[3];
}

// ---------------- kernel 0a: x -> fp16 plane ----------------------------------
__global__ __launch_bounds__(256) void cvt_x(const float* __restrict__ src) {
    const long i = ((long)blockIdx.x * 256 + threadIdx.x) * 4;
    const float4 v = *(const float4*)(src + i);
    __half h[4] = { __float2half_rn(v.x), __float2half_rn(v.y),
                    __float2half_rn(v.z), __float2half_rn(v.w) };
    *(uint2*)(g_x16 + i) = *(uint2*)h;
}

// ---------------- kernel 0b: Wq|Wk|Wv -> fp16 plane (one launch) ---------------
__global__ __launch_bounds__(256) void cvt_w(const float* __restrict__ wq,
                                             const float* __restrict__ wk,
                                             const float* __restrict__ wv) {
    const int mat = blockIdx.y;
    const float* src = (mat == 0) ? wq : ((mat == 1) ? wk : wv);
    const long i = ((long)blockIdx.x * 256 + threadIdx.x) * 4;
    const long o = (long)mat * DIM * DIM + i;
    const float4 v = *(const float4*)(src + i);
    __half h[4] = { __float2half_rn(v.x), __float2half_rn(v.y),
                    __float2half_rn(v.z), __float2half_rn(v.w) };
    *(uint2*)(g_w16 + o) = *(uint2*)h;
}

// ---------------- NT mainloop: k64 double buffer, ONE sync per 64-k -----------
// Rolling prefetch: load sub i of next chunk, compute sub i, store prefetched.
#define NT_BODY(A, B, lda, ldb, NC4)                                           \
    extern __shared__ __align__(128) char dsm[];                               \
    const int tid = threadIdx.x;                                               \
    const int lane = tid & 31, wid = tid >> 5;                                 \
    const int wm = wid >> 1, wn = wid & 1;                                     \
    const uint32_t su = smem_u32(dsm);                                         \
    ACC_INIT;                                                                  \
    _Pragma("unroll")                                                          \
    for (int s = 0; s < 4; ++s)                                                \
        st16_nt(dsm, 0, s, ld16_nt(A, B, lda, ldb, s * 16, tid), tid);         \
    __syncthreads();                                                           \
    for (int c = 0; c < (NC4); ++c) {                                          \
        const int buf = c & 1;                                                 \
        const uint32_t sb0 = su + buf * NT_STG;                                \
        const bool more = (c + 1 < (NC4));                                     \
        const int kn = (c + 1) * 64;                                           \
        Frag4 f;                                                               \
        _Pragma("unroll")                                                      \
        for (int s = 0; s < 4; ++s) {                                          \
            if (more) f = ld16_nt(A, B, lda, ldb, kn + s * 16, tid);           \
            stage_nt(sb0, sb0 + PLANE4, s, lane, wm, wn, acc);                 \
            if (more) st16_nt(dsm, buf ^ 1, s, f, tid);                        \
        }                                                                      \
        if (more) __syncthreads();                                             \
    }

// ---------------- kernel 1: QKV projection (NT) -------------------------------
__global__ __launch_bounds__(128, 2) void gemm_qkv() {
    const int m0 = blockIdx.x * 128;
    const int n0 = blockIdx.y * 128;
    NT_BODY(g_x16 + (long)m0 * DIM, g_w16 + (long)n0 * DIM, DIM, DIM, DIM / 64);

    const int mat = n0 / DIM;
    const int nl0 = n0 % DIM;
    __half* dst = (mat == 0) ? g_q16 : ((mat == 1) ? g_k16 : g_v16);
    const int r = lane >> 2, cc = (lane & 3) * 2;
#pragma unroll
    for (int mi = 0; mi < 4; ++mi)
#pragma unroll
        for (int nj = 0; nj < 8; ++nj)
#pragma unroll
            for (int h2 = 0; h2 < 2; ++h2) {
                const int m = m0 + wm * 64 + mi * 16 + r + h2 * 8;
                const int n = nl0 + wn * 64 + nj * 8 + cc;
                *(__half2*)(dst + (long)m * DIM + n) =
                    __halves2half2(__float2half_rn(acc[mi][nj][h2 * 2 + 0]),
                                   __float2half_rn(acc[mi][nj][h2 * 2 + 1]));
            }
}

// ---------------- kernel 2: causal scores (NT, packed triangular grid) --------
__global__ __launch_bounds__(128, 2) void gemm_scores() {
    // Packed lower-triangle decode, longest rows first.
    const int t = (int)(gridDim.x - 1 - blockIdx.x);
    int mi_t = (int)((sqrtf(8.0f * (float)t + 1.0f) - 1.0f) * 0.5f);
    while ((mi_t + 1) * (mi_t + 2) / 2 <= t) ++mi_t;
    while (mi_t * (mi_t + 1) / 2 > t) --mi_t;
    const int ni = t - mi_t * (mi_t + 1) / 2;
    const int m0 = mi_t * 128, n0 = ni * 128, b = blockIdx.z;
    NT_BODY(g_q16 + ((long)b * SEQ + m0) * DIM,
            g_k16 + ((long)b * SEQ + n0) * DIM, DIM, DIM, DIM / 64);

    const float scale = 0.036084391824351615f;      // 1/sqrt(768)
    float* Sg = g_S + (size_t)b * SEQ * SEQ;
    const int r = lane >> 2, cc = (lane & 3) * 2;
#pragma unroll
    for (int mi = 0; mi < 4; ++mi)
#pragma unroll
        for (int nj = 0; nj < 8; ++nj)
#pragma unroll
            for (int h2 = 0; h2 < 2; ++h2) {
                const int m = m0 + wm * 64 + mi * 16 + r + h2 * 8;
                const int n = n0 + wn * 64 + nj * 8 + cc;
                float2 v = make_float2(acc[mi][nj][h2 * 2 + 0] * scale,
                                       acc[mi][nj][h2 * 2 + 1] * scale);
                *(float2*)(Sg + (size_t)m * SEQ + n) = v;
            }
}

// ---------------- kernel 3: softmax + fp16 P -----------------------------------
__global__ __launch_bounds__(256) void softmax_kernel() {
    const int rid = blockIdx.x;
    const int q = rid & (SEQ - 1);
    float* __restrict__ row = g_S + (size_t)rid * SEQ;
    __half* __restrict__ ph = g_p16 + (size_t)rid * SEQ;
    const int L = q + 1;
    const int tid = threadIdx.x;
    __shared__ float red[256];

    float m = -1e30f;
    for (int k = tid; k < L; k += 256) m = fmaxf(m, row[k]);
    red[tid] = m;
    __syncthreads();
#pragma unroll
    for (int s = 128; s > 0; s >>= 1) {
        if (tid < s) red[tid] = fmaxf(red[tid], red[tid + s]);
        __syncthreads();
    }
    m = red[0];
    __syncthreads();

    float ssum = 0.f;
    for (int k = tid; k < L; k += 256) {
        float e = __expf(row[k] - m);
        row[k] = e;
        ssum += e;
    }
    red[tid] = ssum;
    __syncthreads();
#pragma unroll
    for (int s = 128; s > 0; s >>= 1) {
        if (tid < s) red[tid] += red[tid + s];
        __syncthreads();
    }
    const float inv = 1.0f / red[0];

    for (int k = tid; k < L; k += 256)
        ph[k] = __float2half_rn(row[k] * inv);
    const int kend = (q & ~127) + 128;
    const __half z = __float2half_rn(0.f);
    for (int k = L + tid; k < kend; k += 256) ph[k] = z;
}

// ---------------- kernel 4: O = P V --------------------------------------------
__global__ __launch_bounds__(128, 2) void gemm_pv(float* __restrict__ out) {
    const int mi_t = gridDim.x - 1 - blockIdx.x;    // longest K first
    const int m0 = mi_t * 128, n0 = blockIdx.y * 128, b = blockIdx.z;
    const __half* P = g_p16 + ((size_t)b * SEQ + m0) * SEQ;
    const __half* V = g_v16 + (long)b * SEQ * DIM;

    extern __shared__ __align__(128) char dsm[];
    const int tid = threadIdx.x;
    const int lane = tid & 31, wid = tid >> 5;
    const int wm = wid >> 1, wn = wid & 1;
    const uint32_t su = smem_u32(dsm);
    ACC_INIT;
    const int NC4 = (m0 + 128) / 64;                // >= 2 always

#pragma unroll
    for (int s = 0; s < 4; ++s)
        st16_pv(dsm, 0, s, ld16_pv(P, V, n0, s * 16, tid), tid);
    __syncthreads();
    for (int c = 0; c < NC4; ++c) {
        const int buf = c & 1;
        const uint32_t sb0 = su + buf * PV_STG;
        const bool more = (c + 1 < NC4);
        const int kn = (c + 1) * 64;
        Frag4 f;
#pragma unroll
        for (int s = 0; s < 4; ++s) {
            if (more) f = ld16_pv(P, V, n0, kn + s * 16, tid);
            stage_pv(sb0, sb0 + PLANE4, s, lane, wm, wn, acc);
            if (more) st16_pv(dsm, buf ^ 1, s, f, tid);
        }
        if (more) __syncthreads();
    }

    float* Og = out + (long)b * SEQ * DIM;
    const int r = lane >> 2, cc = (lane & 3) * 2;
#pragma unroll
    for (int mi = 0; mi < 4; ++mi)
#pragma unroll
        for (int nj = 0; nj < 8; ++nj)
#pragma unroll
            for (int h2 = 0; h2 < 2; ++h2) {
                const int m = m0 + wm * 64 + mi * 16 + r + h2 * 8;
                const int n = n0 + wn * 64 + nj * 8 + cc;
                float2 v = make_float2(acc[mi][nj][h2 * 2 + 0],
                                       acc[mi][nj][h2 * 2 + 1]);
                *(float2*)(Og + (long)m * DIM + n) = v;
            }
}

// ---------------- launch ---------------------------------------------------------
extern "C" void kernel_launch(void* const* d_in, const int* in_sizes, int n_in,
                              void* d_out, int out_size) {
    const float* x  = (const float*)d_in[0];
    const float* Wq = (const float*)d_in[1];
    const float* Wk = (const float*)d_in[2];
    const float* Wv = (const float*)d_in[3];
    float* out = (float*)d_out;

    cudaFuncSetAttribute(gemm_qkv,    cudaFuncAttributeMaxDynamicSharedMemorySize, NT_SMEM);
    cudaFuncSetAttribute(gemm_scores, cudaFuncAttributeMaxDynamicSharedMemorySize, NT_SMEM);
    cudaFuncSetAttribute(gemm_pv,     cudaFuncAttributeMaxDynamicSharedMemorySize, PV_SMEM);

    cvt_x<<<(long)MROWS * DIM / 4 / 256, 256>>>(x);
    cvt_w<<<dim3(DIM * DIM / 4 / 256, 3), 256>>>(Wq, Wk, Wv);

    gemm_qkv<<<dim3(MROWS / 128, NQKV / 128), 128, NT_SMEM>>>();
    const int NTILES = (SEQ / 128) * (SEQ / 128 + 1) / 2;   // 136
    gemm_scores<<<dim3(NTILES, 1, BATCH), 128, NT_SMEM>>>();
    softmax_kernel<<<BATCH * SEQ, 256>>>();
    gemm_pv<<<dim3(SEQ / 128, DIM / 128, BATCH), 128, PV_SMEM>>>(out);
}

// round 16
// speedup vs baseline: 1.1785x; 1.0165x over previous
#include <cuda_runtime.h>
#include <cuda_fp16.h>
#include <stdint.h>

#define BATCH 4
#define SEQ   2048
#define DIM   768
#define MROWS 8192            // B*S
#define NQKV  2304            // 3*DIM

// ---------------- device scratch: single fp16 planes --------------------------
__device__ __align__(128) __half g_x16[(long)MROWS * DIM];
__device__ __align__(128) __half g_w16[(long)NQKV * DIM];
__device__ __align__(128) __half g_q16[(long)MROWS * DIM];
__device__ __align__(128) __half g_k16[(long)MROWS * DIM];
__device__ __align__(128) __half g_v16[(long)MROWS * DIM];          // [b*S+s][d]
__device__ __align__(128) __half g_p16[(size_t)BATCH * SEQ * SEQ];
__device__ float g_S[(size_t)BATCH * SEQ * SEQ];

// ---------------- PTX helpers (portable, no arch-'a' features) --------------
__device__ __forceinline__ uint32_t smem_u32(const void* p) {
    uint32_t a;
    asm("{ .reg .u64 t; cvta.to.shared.u64 t, %1; cvt.u32.u64 %0, t; }"
        : "=r"(a) : "l"(p));
    return a;
}
__device__ __forceinline__ void ldsm4(uint32_t r[4], uint32_t addr) {
    asm volatile("ldmatrix.sync.aligned.m8n8.x4.shared.b16 {%0,%1,%2,%3}, [%4];"
                 : "=r"(r[0]), "=r"(r[1]), "=r"(r[2]), "=r"(r[3]) : "r"(addr));
}
__device__ __forceinline__ void ldsm4t(uint32_t r[4], uint32_t addr) {
    asm volatile("ldmatrix.sync.aligned.m8n8.x4.trans.shared.b16 {%0,%1,%2,%3}, [%4];"
                 : "=r"(r[0]), "=r"(r[1]), "=r"(r[2]), "=r"(r[3]) : "r"(addr));
}
__device__ __forceinline__ void mma16816(float d[4], const uint32_t a[4],
                                         const uint32_t b[2]) {
    asm volatile(
        "mma.sync.aligned.m16n8k16.row.col.f32.f16.f16.f32 "
        "{%0,%1,%2,%3}, {%4,%5,%6,%7}, {%8,%9}, {%0,%1,%2,%3};"
        : "+f"(d[0]), "+f"(d[1]), "+f"(d[2]), "+f"(d[3])
        : "r"(a[0]), "r"(a[1]), "r"(a[2]), "r"(a[3]), "r"(b[0]), "r"(b[1]));
}

// ---------------- smem geometry: k64 stages, double buffered ------------------
// pitch 72 halves = 144 B: 16B-aligned; 144 mod 128 = 16 -> conflict-free.
#define ROW4B   144
#define PLANE4  18432                      // 128*144
#define NT_STG  (2 * PLANE4)               // A + B = 36864
#define NT_SMEM (2 * NT_STG)               // 73728

#define VROWB   272
#define VPLANE4 (64 * VROWB)               // 17408
#define PV_STG  (PLANE4 + VPLANE4)         // 35840
#define PV_SMEM (2 * PV_STG)               // 71680

// ---------------- stage compute: warp tile 64x64, one k16 sub (0..3) ----------
__device__ __forceinline__ void stage_nt(uint32_t sa, uint32_t sb, int sub, int lane,
                                         int wm, int wn, float acc[4][8][4]) {
    const int lr = lane & 15;
    const uint32_t lc16 = ((lane >> 4) << 4) + (uint32_t)sub * 32;
    uint32_t bh[8][2];
#pragma unroll
    for (int j = 0; j < 4; ++j) {
        uint32_t t4[4];
        const uint32_t roff = (uint32_t)(wn * 64 + j * 16 + lr) * ROW4B + lc16;
        ldsm4(t4, sb + roff);
        bh[j*2][0] = t4[0]; bh[j*2+1][0] = t4[1];
        bh[j*2][1] = t4[2]; bh[j*2+1][1] = t4[3];
    }
#pragma unroll
    for (int mi = 0; mi < 4; ++mi) {
        uint32_t ah[4];
        const uint32_t roff = (uint32_t)(wm * 64 + mi * 16 + lr) * ROW4B + lc16;
        ldsm4(ah, sa + roff);
#pragma unroll
        for (int nj = 0; nj < 8; ++nj)
            mma16816(acc[mi][nj], ah, bh[nj]);
    }
}

__device__ __forceinline__ void stage_pv(uint32_t sa, uint32_t sv, int sub, int lane,
                                         int wm, int wn, float acc[4][8][4]) {
    const int lr = lane & 15;
    const uint32_t lc16 = (lane >> 4) << 4;
    const uint32_t pc16 = lc16 + (uint32_t)sub * 32;
    uint32_t bh[8][2];
#pragma unroll
    for (int j = 0; j < 4; ++j) {
        uint32_t t4[4];
        const uint32_t off = (uint32_t)(sub * 16 + lr) * VROWB +
                             (uint32_t)(wn * 64 + j * 16) * 2 + lc16;
        ldsm4t(t4, sv + off);
        bh[j*2][0] = t4[0]; bh[j*2][1] = t4[1];
        bh[j*2+1][0] = t4[2]; bh[j*2+1][1] = t4[3];
    }
#pragma unroll
    for (int mi = 0; mi < 4; ++mi) {
        uint32_t ah[4];
        const uint32_t roff = (uint32_t)(wm * 64 + mi * 16 + lr) * ROW4B + pc16;
        ldsm4(ah, sa + roff);
#pragma unroll
        for (int nj = 0; nj < 8; ++nj)
            mma16816(acc[mi][nj], ah, bh[nj]);
    }
}

#define ACC_INIT float acc[4][8][4];                                    \
    _Pragma("unroll") for (int _i = 0; _i < 4; ++_i)                    \
    _Pragma("unroll") for (int _j = 0; _j < 8; ++_j)                    \
    _Pragma("unroll") for (int _k = 0; _k < 4; ++_k) acc[_i][_j][_k] = 0.f;

// ---------------- k16 sub-fill loaders (128 threads, 16-reg rolling prefetch) -
struct Frag4 { uint4 v[4]; };

__device__ __forceinline__ Frag4 ld16_nt(const __half* A, const __half* B,
                                         long lda, long ldb, int k0, int tid) {
    const long ga = (long)tid * lda + k0;
    const long gb = (long)tid * ldb + k0;
    Frag4 f;
    f.v[0] = *(const uint4*)(A + ga);
    f.v[1] = *(const uint4*)(A + ga + 8);
    f.v[2] = *(const uint4*)(B + gb);
    f.v[3] = *(const uint4*)(B + gb + 8);
    return f;
}
__device__ __forceinline__ void st16_nt(char* dsm, int stg, int sub, Frag4 f, int tid) {
    char* base = dsm + stg * NT_STG;
    const uint32_t so = (uint32_t)tid * ROW4B + (uint32_t)sub * 32;
    *(uint4*)(base + so)               = f.v[0];
    *(uint4*)(base + so + 16)          = f.v[1];
    *(uint4*)(base + PLANE4 + so)      = f.v[2];
    *(uint4*)(base + PLANE4 + so + 16) = f.v[3];
}

__device__ __forceinline__ Frag4 ld16_pv(const __half* P, const __half* V,
                                         int n0, int k0, int tid) {
    const long gp = (long)tid * SEQ + k0;
    const int vr = tid >> 3, vc = (tid & 7) * 16;
    const long gv = (long)(k0 + vr) * DIM + n0 + vc;
    Frag4 f;
    f.v[0] = *(const uint4*)(P + gp);
    f.v[1] = *(const uint4*)(P + gp + 8);
    f.v[2] = *(const uint4*)(V + gv);
    f.v[3] = *(const uint4*)(V + gv + 8);
    return f;
}
__device__ __forceinline__ void st16_pv(char* dsm, int stg, int sub, Frag4 f, int tid) {
    char* base = dsm + stg * PV_STG;
    const uint32_t so = (uint32_t)tid * ROW4B + (uint32_t)sub * 32;
    *(uint4*)(base + so)      = f.v[0];
    *(uint4*)(base + so + 16) = f.v[1];
    const int vr = tid >> 3, vc = (tid & 7) * 16;
    const uint32_t vo = (uint32_t)(sub * 16 + vr) * VROWB + (uint32_t)vc * 2;
    *(uint4*)(base + PLANE4 + vo)      = f.v[2];
    *(uint4*)(base + PLANE4 + vo + 16) = f.v[3];
}

// ---------------- kernel 0a: x -> fp16 plane ----------------------------------
__global__ __launch_bounds__(256) void cvt_x(const float* __restrict__ src) {
    const long i = ((long)blockIdx.x * 256 + threadIdx.x) * 4;
    const float4 v = *(const float4*)(src + i);
    __half h[4] = { __float2half_rn(v.x), __float2half_rn(v.y),
                    __float2half_rn(v.z), __float2half_rn(v.w) };
    *(uint2*)(g_x16 + i) = *(uint2*)h;
}

// ---------------- kernel 0b: Wq|Wk|Wv -> fp16 plane (one launch) ---------------
__global__ __launch_bounds__(256) void cvt_w(const float* __restrict__ wq,
                                             const float* __restrict__ wk,
                                             const float* __restrict__ wv) {
    const int mat = blockIdx.y;
    const float* src = (mat == 0) ? wq : ((mat == 1) ? wk : wv);
    const long i = ((long)blockIdx.x * 256 + threadIdx.x) * 4;
    const long o = (long)mat * DIM * DIM + i;
    const float4 v = *(const float4*)(src + i);
    __half h[4] = { __float2half_rn(v.x), __float2half_rn(v.y),
                    __float2half_rn(v.z), __float2half_rn(v.w) };
    *(uint2*)(g_w16 + o) = *(uint2*)h;
}

// ---------------- NT mainloop: k64 double buffer, ONE sync per 64-k -----------
#define NT_BODY(A, B, lda, ldb, NC4)                                           \
    extern __shared__ __align__(128) char dsm[];                               \
    const int tid = threadIdx.x;                                               \
    const int lane = tid & 31, wid = tid >> 5;                                 \
    const int wm = wid >> 1, wn = wid & 1;                                     \
    const uint32_t su = smem_u32(dsm);                                         \
    ACC_INIT;                                                                  \
    _Pragma("unroll")                                                          \
    for (int s = 0; s < 4; ++s)                                                \
        st16_nt(dsm, 0, s, ld16_nt(A, B, lda, ldb, s * 16, tid), tid);         \
    __syncthreads();                                                           \
    for (int c = 0; c < (NC4); ++c) {                                          \
        const int buf = c & 1;                                                 \
        const uint32_t sb0 = su + buf * NT_STG;                                \
        const bool more = (c + 1 < (NC4));                                     \
        const int kn = (c + 1) * 64;                                           \
        Frag4 f;                                                               \
        _Pragma("unroll")                                                      \
        for (int s = 0; s < 4; ++s) {                                          \
            if (more) f = ld16_nt(A, B, lda, ldb, kn + s * 16, tid);           \
            stage_nt(sb0, sb0 + PLANE4, s, lane, wm, wn, acc);                 \
            if (more) st16_nt(dsm, buf ^ 1, s, f, tid);                        \
        }                                                                      \
        if (more) __syncthreads();                                             \
    }

// ---------------- kernel 1: QKV projection (NT) -------------------------------
__global__ __launch_bounds__(128, 2) void gemm_qkv() {
    const int m0 = blockIdx.x * 128;
    const int n0 = blockIdx.y * 128;
    NT_BODY(g_x16 + (long)m0 * DIM, g_w16 + (long)n0 * DIM, DIM, DIM, DIM / 64);

    const int mat = n0 / DIM;
    const int nl0 = n0 % DIM;
    __half* dst = (mat == 0) ? g_q16 : ((mat == 1) ? g_k16 : g_v16);
    const int r = lane >> 2, cc = (lane & 3) * 2;
#pragma unroll
    for (int mi = 0; mi < 4; ++mi)
#pragma unroll
        for (int nj = 0; nj < 8; ++nj)
#pragma unroll
            for (int h2 = 0; h2 < 2; ++h2) {
                const int m = m0 + wm * 64 + mi * 16 + r + h2 * 8;
                const int n = nl0 + wn * 64 + nj * 8 + cc;
                *(__half2*)(dst + (long)m * DIM + n) =
                    __halves2half2(__float2half_rn(acc[mi][nj][h2 * 2 + 0]),
                                   __float2half_rn(acc[mi][nj][h2 * 2 + 1]));
            }
}

// ---------------- kernel 2: causal scores (NT, packed triangular grid) --------
__global__ __launch_bounds__(128, 2) void gemm_scores() {
    const int t = (int)(gridDim.x - 1 - blockIdx.x);   // longest rows first
    int mi_t = (int)((sqrtf(8.0f * (float)t + 1.0f) - 1.0f) * 0.5f);
    while ((mi_t + 1) * (mi_t + 2) / 2 <= t) ++mi_t;
    while (mi_t * (mi_t + 1) / 2 > t) --mi_t;
    const int ni = t - mi_t * (mi_t + 1) / 2;
    const int m0 = mi_t * 128, n0 = ni * 128, b = blockIdx.z;
    NT_BODY(g_q16 + ((long)b * SEQ + m0) * DIM,
            g_k16 + ((long)b * SEQ + n0) * DIM, DIM, DIM, DIM / 64);

    const float scale = 0.036084391824351615f;      // 1/sqrt(768)
    float* Sg = g_S + (size_t)b * SEQ * SEQ;
    const int r = lane >> 2, cc = (lane & 3) * 2;
#pragma unroll
    for (int mi = 0; mi < 4; ++mi)
#pragma unroll
        for (int nj = 0; nj < 8; ++nj)
#pragma unroll
            for (int h2 = 0; h2 < 2; ++h2) {
                const int m = m0 + wm * 64 + mi * 16 + r + h2 * 8;
                const int n = n0 + wn * 64 + nj * 8 + cc;
                float2 v = make_float2(acc[mi][nj][h2 * 2 + 0] * scale,
                                       acc[mi][nj][h2 * 2 + 1] * scale);
                *(float2*)(Sg + (size_t)m * SEQ + n) = v;
            }
}

// ---------------- kernel 3: softmax + fp16 P (vectorized, shuffle reduce) -----
__device__ __forceinline__ float warp_max(float v) {
#pragma unroll
    for (int s = 16; s > 0; s >>= 1)
        v = fmaxf(v, __shfl_xor_sync(0xFFFFFFFFu, v, s));
    return v;
}
__device__ __forceinline__ float warp_sum(float v) {
#pragma unroll
    for (int s = 16; s > 0; s >>= 1)
        v += __shfl_xor_sync(0xFFFFFFFFu, v, s);
    return v;
}

__global__ __launch_bounds__(256) void softmax_kernel() {
    const int rid = blockIdx.x;
    const int q = rid & (SEQ - 1);
    float* __restrict__ row = g_S + (size_t)rid * SEQ;
    __half* __restrict__ ph = g_p16 + (size_t)rid * SEQ;
    const int L = q + 1;
    const int L4 = L >> 2;                 // full float4 groups
    const int tid = threadIdx.x;
    const int lane = tid & 31, wrp = tid >> 5;
    __shared__ float red[8];
    float4* __restrict__ row4 = (float4*)row;

    // pass 1: max
    float m = -1e30f;
    for (int k = tid; k < L4; k += 256) {
        const float4 v = row4[k];
        m = fmaxf(m, fmaxf(fmaxf(v.x, v.y), fmaxf(v.z, v.w)));
    }
    for (int k = L4 * 4 + tid; k < L; k += 256) m = fmaxf(m, row[k]);
    m = warp_max(m);
    if (lane == 0) red[wrp] = m;
    __syncthreads();
    m = warp_max(lane < 8 ? red[lane] : -1e30f);
    m = __shfl_sync(0xFFFFFFFFu, m, 0);

    // pass 2: exp + sum (write exp back as float; cheap, stays in L2)
    float ssum = 0.f;
    for (int k = tid; k < L4; k += 256) {
        float4 v = row4[k];
        v.x = __expf(v.x - m); v.y = __expf(v.y - m);
        v.z = __expf(v.z - m); v.w = __expf(v.w - m);
        ssum += (v.x + v.y) + (v.z + v.w);
        row4[k] = v;
    }
    for (int k = L4 * 4 + tid; k < L; k += 256) {
        const float e = __expf(row[k] - m);
        row[k] = e;
        ssum += e;
    }
    ssum = warp_sum(ssum);
    __syncthreads();                        // red[] reuse hazard
    if (lane == 0) red[wrp] = ssum;
    __syncthreads();
    ssum = warp_sum(lane < 8 ? red[lane] : 0.f);
    const float inv = 1.0f / __shfl_sync(0xFFFFFFFFu, ssum, 0);

    // pass 3: normalize -> fp16 (vector where possible)
    for (int k = tid; k < L4; k += 256) {
        const float4 v = row4[k];
        __half h[4] = { __float2half_rn(v.x * inv), __float2half_rn(v.y * inv),
                        __float2half_rn(v.z * inv), __float2half_rn(v.w * inv) };
        *(uint2*)(ph + k * 4) = *(uint2*)h;
    }
    for (int k = L4 * 4 + tid; k < L; k += 256)
        ph[k] = __float2half_rn(row[k] * inv);
    const int kend = (q & ~127) + 128;
    const __half z = __float2half_rn(0.f);
    for (int k = L + tid; k < kend; k += 256) ph[k] = z;
}

// ---------------- kernel 4: O = P V --------------------------------------------
__global__ __launch_bounds__(128, 2) void gemm_pv(float* __restrict__ out) {
    const int mi_t = gridDim.x - 1 - blockIdx.x;    // longest K first
    const int m0 = mi_t * 128, n0 = blockIdx.y * 128, b = blockIdx.z;
    const __half* P = g_p16 + ((size_t)b * SEQ + m0) * SEQ;
    const __half* V = g_v16 + (long)b * SEQ * DIM;

    extern __shared__ __align__(128) char dsm[];
    const int tid = threadIdx.x;
    const int lane = tid & 31, wid = tid >> 5;
    const int wm = wid >> 1, wn = wid & 1;
    const uint32_t su = smem_u32(dsm);
    ACC_INIT;
    const int NC4 = (m0 + 128) / 64;                // >= 2 always

#pragma unroll
    for (int s = 0; s < 4; ++s)
        st16_pv(dsm, 0, s, ld16_pv(P, V, n0, s * 16, tid), tid);
    __syncthreads();
    for (int c = 0; c < NC4; ++c) {
        const int buf = c & 1;
        const uint32_t sb0 = su + buf * PV_STG;
        const bool more = (c + 1 < NC4);
        const int kn = (c + 1) * 64;
        Frag4 f;
#pragma unroll
        for (int s = 0; s < 4; ++s) {
            if (more) f = ld16_pv(P, V, n0, kn + s * 16, tid);
            stage_pv(sb0, sb0 + PLANE4, s, lane, wm, wn, acc);
            if (more) st16_pv(dsm, buf ^ 1, s, f, tid);
        }
        if (more) __syncthreads();
    }

    float* Og = out + (long)b * SEQ * DIM;
    const int r = lane >> 2, cc = (lane & 3) * 2;
#pragma unroll
    for (int mi = 0; mi < 4; ++mi)
#pragma unroll
        for (int nj = 0; nj < 8; ++nj)
#pragma unroll
            for (int h2 = 0; h2 < 2; ++h2) {
                const int m = m0 + wm * 64 + mi * 16 + r + h2 * 8;
                const int n = n0 + wn * 64 + nj * 8 + cc;
                float2 v = make_float2(acc[mi][nj][h2 * 2 + 0],
                                       acc[mi][nj][h2 * 2 + 1]);
                *(float2*)(Og + (long)m * DIM + n) = v;
            }
}

// ---------------- launch ---------------------------------------------------------
extern "C" void kernel_launch(void* const* d_in, const int* in_sizes, int n_in,
                              void* d_out, int out_size) {
    const float* x  = (const float*)d_in[0];
    const float* Wq = (const float*)d_in[1];
    const float* Wk = (const float*)d_in[2];
    const float* Wv = (const float*)d_in[3];
    float* out = (float*)d_out;

    cudaFuncSetAttribute(gemm_qkv,    cudaFuncAttributeMaxDynamicSharedMemorySize, NT_SMEM);
    cudaFuncSetAttribute(gemm_scores, cudaFuncAttributeMaxDynamicSharedMemorySize, NT_SMEM);
    cudaFuncSetAttribute(gemm_pv,     cudaFuncAttributeMaxDynamicSharedMemorySize, PV_SMEM);

    cvt_x<<<(long)MROWS * DIM / 4 / 256, 256>>>(x);
    cvt_w<<<dim3(DIM * DIM / 4 / 256, 3), 256>>>(Wq, Wk, Wv);

    gemm_qkv<<<dim3(MROWS / 128, NQKV / 128), 128, NT_SMEM>>>();
    const int NTILES = (SEQ / 128) * (SEQ / 128 + 1) / 2;   // 136
    gemm_scores<<<dim3(NTILES, 1, BATCH), 128, NT_SMEM>>>();
    softmax_kernel<<<BATCH * SEQ, 256>>>();
    gemm_pv<<<dim3(SEQ / 128, DIM / 128, BATCH), 128, PV_SMEM>>>(out);
}

// round 17
// speedup vs baseline: 1.2354x; 1.0483x over previous
#include <cuda_runtime.h>
#include <cuda_fp16.h>
#include <stdint.h>

#define BATCH 4
#define SEQ   2048
#define DIM   768
#define MROWS 8192            // B*S
#define NQKV  2304            // 3*DIM

// ---------------- device scratch: single fp16 planes --------------------------
__device__ __align__(128) __half g_x16[(long)MROWS * DIM];
__device__ __align__(128) __half g_w16[(long)NQKV * DIM];
__device__ __align__(128) __half g_q16[(long)MROWS * DIM];
__device__ __align__(128) __half g_k16[(long)MROWS * DIM];
__device__ __align__(128) __half g_v16[(long)MROWS * DIM];          // [b*S+s][d]
__device__ __align__(128) __half g_p16[(size_t)BATCH * SEQ * SEQ];
__device__ float g_S[(size_t)BATCH * SEQ * SEQ];

// ---------------- PTX helpers (portable, no arch-'a' features) --------------
__device__ __forceinline__ uint32_t smem_u32(const void* p) {
    uint32_t a;
    asm("{ .reg .u64 t; cvta.to.shared.u64 t, %1; cvt.u32.u64 %0, t; }"
        : "=r"(a) : "l"(p));
    return a;
}
__device__ __forceinline__ void ldsm4(uint32_t r[4], uint32_t addr) {
    asm volatile("ldmatrix.sync.aligned.m8n8.x4.shared.b16 {%0,%1,%2,%3}, [%4];"
                 : "=r"(r[0]), "=r"(r[1]), "=r"(r[2]), "=r"(r[3]) : "r"(addr));
}
__device__ __forceinline__ void ldsm4t(uint32_t r[4], uint32_t addr) {
    asm volatile("ldmatrix.sync.aligned.m8n8.x4.trans.shared.b16 {%0,%1,%2,%3}, [%4];"
                 : "=r"(r[0]), "=r"(r[1]), "=r"(r[2]), "=r"(r[3]) : "r"(addr));
}
__device__ __forceinline__ void mma16816(float d[4], const uint32_t a[4],
                                         const uint32_t b[2]) {
    asm volatile(
        "mma.sync.aligned.m16n8k16.row.col.f32.f16.f16.f32 "
        "{%0,%1,%2,%3}, {%4,%5,%6,%7}, {%8,%9}, {%0,%1,%2,%3};"
        : "+f"(d[0]), "+f"(d[1]), "+f"(d[2]), "+f"(d[3])
        : "r"(a[0]), "r"(a[1]), "r"(a[2]), "r"(a[3]), "r"(b[0]), "r"(b[1]));
}

// ---------------- smem geometry: k64 stages, pitch 144 B ----------------------
#define ROW4B   144
#define PLANE4  18432                      // 128*144 (128-row plane)
#define NT_STG  (2 * PLANE4)               // A + B = 36864
#define NT_SMEM (2 * NT_STG)               // 73728

#define APLANEQ 36864                      // 256*144 (256-row A plane, qkv)
#define Q_STG   (APLANEQ + PLANE4)         // 55296
#define Q_SMEM  (2 * Q_STG)                // 110592

#define VROWB   272
#define VPLANE4 (64 * VROWB)               // 17408
#define PV_STG  (PLANE4 + VPLANE4)         // 35840
#define PV_SMEM (2 * PV_STG)               // 71680

// ---------------- stage compute: warp tile 64x64, one k16 sub (0..3) ----------
// Generic over warp coords: A rows wm*64.., B rows wn*64.. (within own plane).
__device__ __forceinline__ void stage_nt(uint32_t sa, uint32_t sb, int sub, int lane,
                                         int wm, int wn, float acc[4][8][4]) {
    const int lr = lane & 15;
    const uint32_t lc16 = ((lane >> 4) << 4) + (uint32_t)sub * 32;
    uint32_t bh[8][2];
#pragma unroll
    for (int j = 0; j < 4; ++j) {
        uint32_t t4[4];
        const uint32_t roff = (uint32_t)(wn * 64 + j * 16 + lr) * ROW4B + lc16;
        ldsm4(t4, sb + roff);
        bh[j*2][0] = t4[0]; bh[j*2+1][0] = t4[1];
        bh[j*2][1] = t4[2]; bh[j*2+1][1] = t4[3];
    }
#pragma unroll
    for (int mi = 0; mi < 4; ++mi) {
        uint32_t ah[4];
        const uint32_t roff = (uint32_t)(wm * 64 + mi * 16 + lr) * ROW4B + lc16;
        ldsm4(ah, sa + roff);
#pragma unroll
        for (int nj = 0; nj < 8; ++nj)
            mma16816(acc[mi][nj], ah, bh[nj]);
    }
}

__device__ __forceinline__ void stage_pv(uint32_t sa, uint32_t sv, int sub, int lane,
                                         int wm, int wn, float acc[4][8][4]) {
    const int lr = lane & 15;
    const uint32_t lc16 = (lane >> 4) << 4;
    const uint32_t pc16 = lc16 + (uint32_t)sub * 32;
    uint32_t bh[8][2];
#pragma unroll
    for (int j = 0; j < 4; ++j) {
        uint32_t t4[4];
        const uint32_t off = (uint32_t)(sub * 16 + lr) * VROWB +
                             (uint32_t)(wn * 64 + j * 16) * 2 + lc16;
        ldsm4t(t4, sv + off);
        bh[j*2][0] = t4[0]; bh[j*2][1] = t4[1];
        bh[j*2+1][0] = t4[2]; bh[j*2+1][1] = t4[3];
    }
#pragma unroll
    for (int mi = 0; mi < 4; ++mi) {
        uint32_t ah[4];
        const uint32_t roff = (uint32_t)(wm * 64 + mi * 16 + lr) * ROW4B + pc16;
        ldsm4(ah, sa + roff);
#pragma unroll
        for (int nj = 0; nj < 8; ++nj)
            mma16816(acc[mi][nj], ah, bh[nj]);
    }
}

#define ACC_INIT float acc[4][8][4];                                    \
    _Pragma("unroll") for (int _i = 0; _i < 4; ++_i)                    \
    _Pragma("unroll") for (int _j = 0; _j < 8; ++_j)                    \
    _Pragma("unroll") for (int _k = 0; _k < 4; ++_k) acc[_i][_j][_k] = 0.f;

// ---------------- loaders: scores (128 thr) -----------------------------------
struct Frag4 { uint4 v[4]; };

__device__ __forceinline__ Frag4 ld16_nt(const __half* A, const __half* B,
                                         long lda, long ldb, int k0, int tid) {
    const long ga = (long)tid * lda + k0;
    const long gb = (long)tid * ldb + k0;
    Frag4 f;
    f.v[0] = *(const uint4*)(A + ga);
    f.v[1] = *(const uint4*)(A + ga + 8);
    f.v[2] = *(const uint4*)(B + gb);
    f.v[3] = *(const uint4*)(B + gb + 8);
    return f;
}
__device__ __forceinline__ void st16_nt(char* dsm, int stg, int sub, Frag4 f, int tid) {
    char* base = dsm + stg * NT_STG;
    const uint32_t so = (uint32_t)tid * ROW4B + (uint32_t)sub * 32;
    *(uint4*)(base + so)               = f.v[0];
    *(uint4*)(base + so + 16)          = f.v[1];
    *(uint4*)(base + PLANE4 + so)      = f.v[2];
    *(uint4*)(base + PLANE4 + so + 16) = f.v[3];
}

// ---------------- loaders: qkv 256x128 (256 thr) -------------------------------
struct Frag3 { uint4 v[3]; };

__device__ __forceinline__ Frag3 ld16_q(const __half* A, const __half* B,
                                        int k0, int tid) {
    const long ga = (long)tid * DIM + k0;                  // A row = tid (0..255)
    const int rb = tid >> 1, hb = tid & 1;                 // B row, 16B half
    const long gb = (long)rb * DIM + k0 + hb * 8;
    Frag3 f;
    f.v[0] = *(const uint4*)(A + ga);
    f.v[1] = *(const uint4*)(A + ga + 8);
    f.v[2] = *(const uint4*)(B + gb);
    return f;
}
__device__ __forceinline__ void st16_q(char* dsm, int stg, int sub, Frag3 f, int tid) {
    char* base = dsm + stg * Q_STG;
    const uint32_t so = (uint32_t)tid * ROW4B + (uint32_t)sub * 32;
    *(uint4*)(base + so)      = f.v[0];
    *(uint4*)(base + so + 16) = f.v[1];
    const int rb = tid >> 1, hb = tid & 1;
    const uint32_t sob = (uint32_t)rb * ROW4B + (uint32_t)sub * 32 + (uint32_t)hb * 16;
    *(uint4*)(base + APLANEQ + sob) = f.v[2];
}

// ---------------- loaders: pv (128 thr) ----------------------------------------
__device__ __forceinline__ Frag4 ld16_pv(const __half* P, const __half* V,
                                         int n0, int k0, int tid) {
    const long gp = (long)tid * SEQ + k0;
    const int vr = tid >> 3, vc = (tid & 7) * 16;
    const long gv = (long)(k0 + vr) * DIM + n0 + vc;
    Frag4 f;
    f.v[0] = *(const uint4*)(P + gp);
    f.v[1] = *(const uint4*)(P + gp + 8);
    f.v[2] = *(const uint4*)(V + gv);
    f.v[3] = *(const uint4*)(V + gv + 8);
    return f;
}
__device__ __forceinline__ void st16_pv(char* dsm, int stg, int sub, Frag4 f, int tid) {
    char* base = dsm + stg * PV_STG;
    const uint32_t so = (uint32_t)tid * ROW4B + (uint32_t)sub * 32;
    *(uint4*)(base + so)      = f.v[0];
    *(uint4*)(base + so + 16) = f.v[1];
    const int vr = tid >> 3, vc = (tid & 7) * 16;
    const uint32_t vo = (uint32_t)(sub * 16 + vr) * VROWB + (uint32_t)vc * 2;
    *(uint4*)(base + PLANE4 + vo)      = f.v[2];
    *(uint4*)(base + PLANE4 + vo + 16) = f.v[3];
}

// ---------------- kernel 0: x | Wq|Wk|Wv -> fp16 planes (single launch) --------
__global__ __launch_bounds__(256) void cvt_all(const float* __restrict__ x,
                                               const float* __restrict__ wq,
                                               const float* __restrict__ wk,
                                               const float* __restrict__ wv) {
    const int seg = blockIdx.y;            // 0 = x, 1..3 = W
    const float* src;
    __half* dst;
    if (seg == 0) { src = x; dst = g_x16; }
    else {
        src = (seg == 1) ? wq : ((seg == 2) ? wk : wv);
        dst = g_w16 + (long)(seg - 1) * DIM * DIM;
    }
    const long i = ((long)blockIdx.x * 256 + threadIdx.x) * 4;
    if (seg > 0 && i >= (long)DIM * DIM) return;
    const float4 v = *(const float4*)(src + i);
    __half h[4] = { __float2half_rn(v.x), __float2half_rn(v.y),
                    __float2half_rn(v.z), __float2half_rn(v.w) };
    *(uint2*)(dst + i) = *(uint2*)h;
}

// ---------------- kernel 1: QKV projection, 256x128 CTA tile -------------------
__global__ __launch_bounds__(256, 1) void gemm_qkv() {
    extern __shared__ __align__(128) char dsm[];
    const int tid = threadIdx.x;
    const int lane = tid & 31, wid = tid >> 5;
    const int wm = wid >> 1, wn = wid & 1;            // wm 0..3, wn 0..1
    const uint32_t su = smem_u32(dsm);
    const int m0 = blockIdx.x * 256;
    const int n0 = blockIdx.y * 128;
    const __half* A = g_x16 + (long)m0 * DIM;
    const __half* B = g_w16 + (long)n0 * DIM;
    ACC_INIT;

#pragma unroll
    for (int s = 0; s < 4; ++s)
        st16_q(dsm, 0, s, ld16_q(A, B, s * 16, tid), tid);
    __syncthreads();
    const int NC4 = DIM / 64;
    for (int c = 0; c < NC4; ++c) {
        const int buf = c & 1;
        const uint32_t sb0 = su + buf * Q_STG;
        const bool more = (c + 1 < NC4);
        const int kn = (c + 1) * 64;
        Frag3 f;
#pragma unroll
        for (int s = 0; s < 4; ++s) {
            if (more) f = ld16_q(A, B, kn + s * 16, tid);
            stage_nt(sb0, sb0 + APLANEQ, s, lane, wm, wn, acc);
            if (more) st16_q(dsm, buf ^ 1, s, f, tid);
        }
        if (more) __syncthreads();
    }

    const int mat = n0 / DIM;
    const int nl0 = n0 % DIM;
    __half* dst = (mat == 0) ? g_q16 : ((mat == 1) ? g_k16 : g_v16);
    const int r = lane >> 2, cc = (lane & 3) * 2;
#pragma unroll
    for (int mi = 0; mi < 4; ++mi)
#pragma unroll
        for (int nj = 0; nj < 8; ++nj)
#pragma unroll
            for (int h2 = 0; h2 < 2; ++h2) {
                const int m = m0 + wm * 64 + mi * 16 + r + h2 * 8;
                const int n = nl0 + wn * 64 + nj * 8 + cc;
                *(__half2*)(dst + (long)m * DIM + n) =
                    __halves2half2(__float2half_rn(acc[mi][nj][h2 * 2 + 0]),
                                   __float2half_rn(acc[mi][nj][h2 * 2 + 1]));
            }
}

// ---------------- scores mainloop macro (128 thr, k64 double buffer) -----------
#define NT_BODY(A, B, lda, ldb, NC4)                                           \
    extern __shared__ __align__(128) char dsm[];                               \
    const int tid = threadIdx.x;                                               \
    const int lane = tid & 31, wid = tid >> 5;                                 \
    const int wm = wid >> 1, wn = wid & 1;                                     \
    const uint32_t su = smem_u32(dsm);                                         \
    ACC_INIT;                                                                  \
    _Pragma("unroll")                                                          \
    for (int s = 0; s < 4; ++s)                                                \
        st16_nt(dsm, 0, s, ld16_nt(A, B, lda, ldb, s * 16, tid), tid);         \
    __syncthreads();                                                           \
    for (int c = 0; c < (NC4); ++c) {                                          \
        const int buf = c & 1;                                                 \
        const uint32_t sb0 = su + buf * NT_STG;                                \
        const bool more = (c + 1 < (NC4));                                     \
        const int kn = (c + 1) * 64;                                           \
        Frag4 f;                                                               \
        _Pragma("unroll")                                                      \
        for (int s = 0; s < 4; ++s) {                                          \
            if (more) f = ld16_nt(A, B, lda, ldb, kn + s * 16, tid);           \
            stage_nt(sb0, sb0 + PLANE4, s, lane, wm, wn, acc);                 \
            if (more) st16_nt(dsm, buf ^ 1, s, f, tid);                        \
        }                                                                      \
        if (more) __syncthreads();                                             \
    }

// ---------------- kernel 2: causal scores (NT, packed triangular grid) --------
__global__ __launch_bounds__(128, 2) void gemm_scores() {
    const int t = (int)(gridDim.x - 1 - blockIdx.x);   // longest rows first
    int mi_t = (int)((sqrtf(8.0f * (float)t + 1.0f) - 1.0f) * 0.5f);
    while ((mi_t + 1) * (mi_t + 2) / 2 <= t) ++mi_t;
    while (mi_t * (mi_t + 1) / 2 > t) --mi_t;
    const int ni = t - mi_t * (mi_t + 1) / 2;
    const int m0 = mi_t * 128, n0 = ni * 128, b = blockIdx.z;
    NT_BODY(g_q16 + ((long)b * SEQ + m0) * DIM,
            g_k16 + ((long)b * SEQ + n0) * DIM, DIM, DIM, DIM / 64);

    const float scale = 0.036084391824351615f;      // 1/sqrt(768)
    float* Sg = g_S + (size_t)b * SEQ * SEQ;
    const int r = lane >> 2, cc = (lane & 3) * 2;
#pragma unroll
    for (int mi = 0; mi < 4; ++mi)
#pragma unroll
        for (int nj = 0; nj < 8; ++nj)
#pragma unroll
            for (int h2 = 0; h2 < 2; ++h2) {
                const int m = m0 + wm * 64 + mi * 16 + r + h2 * 8;
                const int n = n0 + wn * 64 + nj * 8 + cc;
                float2 v = make_float2(acc[mi][nj][h2 * 2 + 0] * scale,
                                       acc[mi][nj][h2 * 2 + 1] * scale);
                *(float2*)(Sg + (size_t)m * SEQ + n) = v;
            }
}

// ---------------- kernel 3: softmax + fp16 P (vectorized, shuffle reduce) -----
__device__ __forceinline__ float warp_max(float v) {
#pragma unroll
    for (int s = 16; s > 0; s >>= 1)
        v = fmaxf(v, __shfl_xor_sync(0xFFFFFFFFu, v, s));
    return v;
}
__device__ __forceinline__ float warp_sum(float v) {
#pragma unroll
    for (int s = 16; s > 0; s >>= 1)
        v += __shfl_xor_sync(0xFFFFFFFFu, v, s);
    return v;
}

__global__ __launch_bounds__(256) void softmax_kernel() {
    const int rid = blockIdx.x;
    const int q = rid & (SEQ - 1);
    float* __restrict__ row = g_S + (size_t)rid * SEQ;
    __half* __restrict__ ph = g_p16 + (size_t)rid * SEQ;
    const int L = q + 1;
    const int L4 = L >> 2;
    const int tid = threadIdx.x;
    const int lane = tid & 31, wrp = tid >> 5;
    __shared__ float red[8];
    float4* __restrict__ row4 = (float4*)row;

    float m = -1e30f;
    for (int k = tid; k < L4; k += 256) {
        const float4 v = row4[k];
        m = fmaxf(m, fmaxf(fmaxf(v.x, v.y), fmaxf(v.z, v.w)));
    }
    for (int k = L4 * 4 + tid; k < L; k += 256) m = fmaxf(m, row[k]);
    m = warp_max(m);
    if (lane == 0) red[wrp] = m;
    __syncthreads();
    m = warp_max(lane < 8 ? red[lane] : -1e30f);
    m = __shfl_sync(0xFFFFFFFFu, m, 0);

    float ssum = 0.f;
    for (int k = tid; k < L4; k += 256) {
        float4 v = row4[k];
        v.x = __expf(v.x - m); v.y = __expf(v.y - m);
        v.z = __expf(v.z - m); v.w = __expf(v.w - m);
        ssum += (v.x + v.y) + (v.z + v.w);
        row4[k] = v;
    }
    for (int k = L4 * 4 + tid; k < L; k += 256) {
        const float e = __expf(row[k] - m);
        row[k] = e;
        ssum += e;
    }
    ssum = warp_sum(ssum);
    __syncthreads();
    if (lane == 0) red[wrp] = ssum;
    __syncthreads();
    ssum = warp_sum(lane < 8 ? red[lane] : 0.f);
    const float inv = 1.0f / __shfl_sync(0xFFFFFFFFu, ssum, 0);

    for (int k = tid; k < L4; k += 256) {
        const float4 v = row4[k];
        __half h[4] = { __float2half_rn(v.x * inv), __float2half_rn(v.y * inv),
                        __float2half_rn(v.z * inv), __float2half_rn(v.w * inv) };
        *(uint2*)(ph + k * 4) = *(uint2*)h;
    }
    for (int k = L4 * 4 + tid; k < L; k += 256)
        ph[k] = __float2half_rn(row[k] * inv);
    const int kend = (q & ~127) + 128;
    const __half z = __float2half_rn(0.f);
    for (int k = L + tid; k < kend; k += 256) ph[k] = z;
}

// ---------------- kernel 4: O = P V --------------------------------------------
__global__ __launch_bounds__(128, 2) void gemm_pv(float* __restrict__ out) {
    const int mi_t = gridDim.x - 1 - blockIdx.x;    // longest K first
    const int m0 = mi_t * 128, n0 = blockIdx.y * 128, b = blockIdx.z;
    const __half* P = g_p16 + ((size_t)b * SEQ + m0) * SEQ;
    const __half* V = g_v16 + (long)b * SEQ * DIM;

    extern __shared__ __align__(128) char dsm[];
    const int tid = threadIdx.x;
    const int lane = tid & 31, wid = tid >> 5;
    const int wm = wid >> 1, wn = wid & 1;
    const uint32_t su = smem_u32(dsm);
    ACC_INIT;
    const int NC4 = (m0 + 128) / 64;

#pragma unroll
    for (int s = 0; s < 4; ++s)
        st16_pv(dsm, 0, s, ld16_pv(P, V, n0, s * 16, tid), tid);
    __syncthreads();
    for (int c = 0; c < NC4; ++c) {
        const int buf = c & 1;
        const uint32_t sb0 = su + buf * PV_STG;
        const bool more = (c + 1 < NC4);
        const int kn = (c + 1) * 64;
        Frag4 f;
#pragma unroll
        for (int s = 0; s < 4; ++s) {
            if (more) f = ld16_pv(P, V, n0, kn + s * 16, tid);
            stage_pv(sb0, sb0 + PLANE4, s, lane, wm, wn, acc);
            if (more) st16_pv(dsm, buf ^ 1, s, f, tid);
        }
        if (more) __syncthreads();
    }

    float* Og = out + (long)b * SEQ * DIM;
    const int r = lane >> 2, cc = (lane & 3) * 2;
#pragma unroll
    for (int mi = 0; mi < 4; ++mi)
#pragma unroll
        for (int nj = 0; nj < 8; ++nj)
#pragma unroll
            for (int h2 = 0; h2 < 2; ++h2) {
                const int m = m0 + wm * 64 + mi * 16 + r + h2 * 8;
                const int n = n0 + wn * 64 + nj * 8 + cc;
                float2 v = make_float2(acc[mi][nj][h2 * 2 + 0],
                                       acc[mi][nj][h2 * 2 + 1]);
                *(float2*)(Og + (long)m * DIM + n) = v;
            }
}

// ---------------- launch ---------------------------------------------------------
extern "C" void kernel_launch(void* const* d_in, const int* in_sizes, int n_in,
                              void* d_out, int out_size) {
    const float* x  = (const float*)d_in[0];
    const float* Wq = (const float*)d_in[1];
    const float* Wk = (const float*)d_in[2];
    const float* Wv = (const float*)d_in[3];
    float* out = (float*)d_out;

    cudaFuncSetAttribute(gemm_qkv,    cudaFuncAttributeMaxDynamicSharedMemorySize, Q_SMEM);
    cudaFuncSetAttribute(gemm_scores, cudaFuncAttributeMaxDynamicSharedMemorySize, NT_SMEM);
    cudaFuncSetAttribute(gemm_pv,     cudaFuncAttributeMaxDynamicSharedMemorySize, PV_SMEM);

    // x is the largest conversion; grid.x sized for x, W segments early-exit.
    cvt_all<<<dim3((long)MROWS * DIM / 4 / 256, 4), 256>>>(x, Wq, Wk, Wv);

    gemm_qkv<<<dim3(MROWS / 256, NQKV / 128), 256, Q_SMEM>>>();
    const int NTILES = (SEQ / 128) * (SEQ / 128 + 1) / 2;   // 136
    gemm_scores<<<dim3(NTILES, 1, BATCH), 128, NT_SMEM>>>();
    softmax_kernel<<<BATCH * SEQ, 256>>>();
    gemm_pv<<<dim3(SEQ / 128, DIM / 128, BATCH), 128, PV_SMEM>>>(out);
}